// round 10
// baseline (speedup 1.0000x reference)
#include <cuda_runtime.h>
#include <cuda_bf16.h>
#include <cstdint>
#include <math.h>

// Problem constants
#define S_LEN 4096
#define D_MODEL 512
#define SLOPE 0.5f
#define QT 32
#define NKEY 128
#define WBACK 96
#define NB 4

// Scratch
__device__ float g_Q[NB * S_LEN * D_MODEL];     // tf32-rounded floats
__device__ float g_V[NB * S_LEN * D_MODEL];     // tf32-rounded floats (bias added)
__device__ uint32_t g_Xt[NB * S_LEN * D_MODEL]; // X pre-rounded to tf32
__device__ uint32_t g_Wt[1024 * 512];           // [Wqk | Wv^T] tf32, [n][k]

// ---------------------------------------------------------------------------
// Helpers
// ---------------------------------------------------------------------------
__device__ __forceinline__ void mma16808(float* d, const uint32_t* a,
                                         uint32_t b0, uint32_t b1)
{
    asm volatile(
        "mma.sync.aligned.m16n8k8.row.col.f32.tf32.tf32.f32 "
        "{%0,%1,%2,%3}, {%4,%5,%6,%7}, {%8,%9}, {%0,%1,%2,%3};"
        : "+f"(d[0]), "+f"(d[1]), "+f"(d[2]), "+f"(d[3])
        : "r"(a[0]), "r"(a[1]), "r"(a[2]), "r"(a[3]), "r"(b0), "r"(b1));
}

__device__ __forceinline__ uint32_t f2tf32(float x) {
    uint32_t t;
    asm("cvt.rna.tf32.f32 %0, %1;" : "=r"(t) : "f"(x));
    return t;
}

__device__ __forceinline__ void cpa16(uint32_t dst, const void* src) {
    asm volatile("cp.async.cg.shared.global [%0], [%1], 16;"
                 :: "r"(dst), "l"(src) : "memory");
}
__device__ __forceinline__ void sts_zero16(uint32_t dst) {
    asm volatile("st.shared.v4.b32 [%0], {%1,%1,%1,%1};" :: "r"(dst), "r"(0u)
                 : "memory");
}
#define CPA_COMMIT() asm volatile("cp.async.commit_group;" ::: "memory")
#define CPA_WAIT0()  asm volatile("cp.async.wait_group 0;" ::: "memory")

// ---------------------------------------------------------------------------
// pack_all: X -> tf32 (g_Xt), [Wqk | Wv^T] -> tf32 (g_Wt)
// ---------------------------------------------------------------------------
__global__ void pack_all(const float* __restrict__ X,
                         const float* __restrict__ Wqk,
                         const float* __restrict__ Wv)
{
    int bid = blockIdx.x;
    if (bid < 8192) {
        int idx = bid * 256 + threadIdx.x;       // float4 over X
        float4 v = reinterpret_cast<const float4*>(X)[idx];
        uint4 t;
        t.x = f2tf32(v.x); t.y = f2tf32(v.y);
        t.z = f2tf32(v.z); t.w = f2tf32(v.w);
        reinterpret_cast<uint4*>(g_Xt)[idx] = t;
    } else {
        int idx = (bid - 8192) * 256 + threadIdx.x;   // 0..524287
        int n = idx >> 9, k = idx & 511;
        float w = (n < 512) ? Wqk[k * 512 + n] : Wv[(n - 512) * 512 + k];
        g_Wt[idx] = f2tf32(w);
    }
}

// ---------------------------------------------------------------------------
// tf32 mma GEMM: [Q|V][16384, 1024] = Xt[16384,512] @ W^T  (unchanged — at
// the legacy-HMMA issue ceiling already)
// ---------------------------------------------------------------------------
#define STRF 68
#define APLANE (128 * STRF)

__global__ __launch_bounds__(256)
void mma_gemm(const float* __restrict__ bias,
              float* __restrict__ Q, float* __restrict__ V)
{
    extern __shared__ uint32_t smw[];
    uint32_t* sA = smw;
    uint32_t* sB = smw + APLANE;

    const int tid = threadIdx.x;
    const int wid = tid >> 5;
    const int lane = tid & 31;
    const int g = lane >> 2;
    const int t4 = lane & 3;
    const int warp_m = wid & 3;
    const int warp_n = wid >> 2;
    const int m0 = blockIdx.x * 128;
    const int n0 = blockIdx.y * 128;

    float acc[2][8][4];
#pragma unroll
    for (int mt = 0; mt < 2; mt++)
#pragma unroll
        for (int nt = 0; nt < 8; nt++)
#pragma unroll
            for (int i = 0; i < 4; i++) acc[mt][nt][i] = 0.f;

    const int lrow = tid >> 4;
    const int lc4  = (tid & 15) << 2;

    for (int c = 0; c < 8; c++) {
        const int k0 = c * 64;
        uint4 av[8], bv[8];
#pragma unroll
        for (int i = 0; i < 8; i++) {
            int row = lrow + 16 * i;
            av[i] = *reinterpret_cast<const uint4*>(
                &g_Xt[(size_t)(m0 + row) * 512 + k0 + lc4]);
            bv[i] = *reinterpret_cast<const uint4*>(
                &g_Wt[(size_t)(n0 + row) * 512 + k0 + lc4]);
        }
        if (c) __syncthreads();
#pragma unroll
        for (int i = 0; i < 8; i++) {
            int row = lrow + 16 * i;
            *reinterpret_cast<uint4*>(&sA[row * STRF + lc4]) = av[i];
            *reinterpret_cast<uint4*>(&sB[row * STRF + lc4]) = bv[i];
        }
        __syncthreads();
#pragma unroll
        for (int k8 = 0; k8 < 8; k8++) {
            const int kc = k8 * 8 + t4;
            uint32_t a[2][4];
#pragma unroll
            for (int mt = 0; mt < 2; mt++) {
                int r = warp_m * 32 + mt * 16 + g;
                a[mt][0] = sA[r * STRF + kc];
                a[mt][1] = sA[(r + 8) * STRF + kc];
                a[mt][2] = sA[r * STRF + kc + 4];
                a[mt][3] = sA[(r + 8) * STRF + kc + 4];
            }
#pragma unroll
            for (int nt = 0; nt < 8; nt++) {
                int rn = warp_n * 64 + nt * 8 + g;
                uint32_t b0 = sB[rn * STRF + kc];
                uint32_t b1 = sB[rn * STRF + kc + 4];
#pragma unroll
                for (int mt = 0; mt < 2; mt++)
                    mma16808(acc[mt][nt], a[mt], b0, b1);
            }
        }
    }

#pragma unroll
    for (int mt = 0; mt < 2; mt++) {
        int row0 = m0 + warp_m * 32 + mt * 16 + g;
#pragma unroll
        for (int nt = 0; nt < 8; nt++) {
            int col = n0 + warp_n * 64 + nt * 8 + t4 * 2;
            if (col < 512) {
                float2 lo = make_float2(
                    __uint_as_float(f2tf32(acc[mt][nt][0])),
                    __uint_as_float(f2tf32(acc[mt][nt][1])));
                float2 hi = make_float2(
                    __uint_as_float(f2tf32(acc[mt][nt][2])),
                    __uint_as_float(f2tf32(acc[mt][nt][3])));
                *reinterpret_cast<float2*>(&Q[(size_t)row0 * 512 + col]) = lo;
                *reinterpret_cast<float2*>(&Q[(size_t)(row0 + 8) * 512 + col]) = hi;
            } else {
                int vc = col - 512;
                float2 b2 = *reinterpret_cast<const float2*>(&bias[vc]);
                float2 lo = make_float2(
                    __uint_as_float(f2tf32(acc[mt][nt][0] + b2.x)),
                    __uint_as_float(f2tf32(acc[mt][nt][1] + b2.y)));
                float2 hi = make_float2(
                    __uint_as_float(f2tf32(acc[mt][nt][2] + b2.x)),
                    __uint_as_float(f2tf32(acc[mt][nt][3] + b2.y)));
                *reinterpret_cast<float2*>(&V[(size_t)row0 * 512 + vc]) = lo;
                *reinterpret_cast<float2*>(&V[(size_t)(row0 + 8) * 512 + vc]) = hi;
            }
        }
    }
}

// ---------------------------------------------------------------------------
// Tensor-core windowed attention, occupancy-3 layout (61.5 KB smem).
// CTA = 32 queries x 128-key band, 8 warps, 3 CTAs/SM.
// Phase1: 16 half-chunks of 32 k-cols, double-buffered Q/K (stride 36 words).
// Phase3: 8 chunks of 64 features, single-buffered V (stride 72), aliased.
// ---------------------------------------------------------------------------
#define SP_STR 132
#define HK_STR 36
#define VC_STR 72
#define W_Q0 4224
#define W_Q1 (W_Q0 + 32 * HK_STR)        // 5376
#define W_K0 (W_Q1 + 32 * HK_STR)        // 6528
#define W_K1 (W_K0 + 128 * HK_STR)       // 11136
#define W_V0 4224                        // aliased over phase1 buffers
#define ATTN_W (W_K1 + 128 * HK_STR)     // 15744 words = 62976 B

__global__ __launch_bounds__(256, 3)
void attn_tc(const float* __restrict__ Q, const float* __restrict__ V,
             float* __restrict__ O)
{
    extern __shared__ uint32_t smw[];
    float* sP = reinterpret_cast<float*>(smw);
    const uint32_t sbase = (uint32_t)__cvta_generic_to_shared(smw);

    const int tid = threadIdx.x;
    const int wid = tid >> 5;
    const int lane = tid & 31;
    const int g = lane >> 2;
    const int t4 = lane & 3;
    const int b  = blockIdx.y;
    const int i0 = blockIdx.x * QT;
    const int jstart = i0 - WBACK;

    const float* Qb = Q + (size_t)b * S_LEN * D_MODEL;
    const float* Vb = V + (size_t)b * S_LEN * D_MODEL;
    const uint32_t* Kb = g_Xt + (size_t)b * S_LEN * D_MODEL;

    const int wm = wid & 1;
    const int wn = wid >> 1;      // 0..3

    // ---- phase-1 half-chunk loader: 32 k-cols (Q: 1 cp16/thr, K: 4/thr) ----
    const int qrow = tid >> 3;            // 0..31
    const int qc4  = (tid & 7) << 2;      // 0..28

    // prologue: half-chunk 0
    {
        cpa16(sbase + (W_Q0 + qrow * HK_STR + qc4) * 4,
              &Qb[(size_t)(i0 + qrow) * 512 + 0 + qc4]);
#pragma unroll
        for (int i = 0; i < 4; i++) {
            int idx = tid + 256 * i;
            int row = idx >> 3, c4 = (idx & 7) << 2;
            int j = jstart + row;
            uint32_t dst = sbase + (W_K0 + row * HK_STR + c4) * 4;
            if (j >= 0) cpa16(dst, &Kb[(size_t)j * 512 + 0 + c4]);
            else sts_zero16(dst);
        }
        CPA_COMMIT();
    }

    float accs[4][4];
#pragma unroll
    for (int nt = 0; nt < 4; nt++)
#pragma unroll
        for (int i = 0; i < 4; i++) accs[nt][i] = 0.f;

    for (int hc = 0; hc < 16; hc++) {
        CPA_WAIT0();
        __syncthreads();
        if (hc < 15) {
            const int k0 = (hc + 1) * 32;
            const int wq = ((hc + 1) & 1) ? W_Q1 : W_Q0;
            const int wk = ((hc + 1) & 1) ? W_K1 : W_K0;
            cpa16(sbase + (wq + qrow * HK_STR + qc4) * 4,
                  &Qb[(size_t)(i0 + qrow) * 512 + k0 + qc4]);
#pragma unroll
            for (int i = 0; i < 4; i++) {
                int idx = tid + 256 * i;
                int row = idx >> 3, c4 = (idx & 7) << 2;
                int j = jstart + row;
                uint32_t dst = sbase + (wk + row * HK_STR + c4) * 4;
                if (j >= 0) cpa16(dst, &Kb[(size_t)j * 512 + k0 + c4]);
                else sts_zero16(dst);
            }
            CPA_COMMIT();
        }
        const uint32_t* sQ = smw + ((hc & 1) ? W_Q1 : W_Q0);
        const uint32_t* sK = smw + ((hc & 1) ? W_K1 : W_K0);
#pragma unroll
        for (int k8 = 0; k8 < 4; k8++) {
            const int kc = k8 * 8 + t4;
            uint32_t a[4];
            int r = wm * 16 + g;
            a[0] = sQ[r * HK_STR + kc];
            a[1] = sQ[(r + 8) * HK_STR + kc];
            a[2] = sQ[r * HK_STR + kc + 4];
            a[3] = sQ[(r + 8) * HK_STR + kc + 4];
#pragma unroll
            for (int nt = 0; nt < 4; nt++) {
                int rn = wn * 32 + nt * 8 + g;
                uint32_t b0 = sK[rn * HK_STR + kc];
                uint32_t b1 = sK[rn * HK_STR + kc + 4];
                mma16808(accs[nt], a, b0, b1);
            }
        }
    }
    __syncthreads();   // phase-1 buffers dead; sP region still live below

    // scale + ALiBi + causal mask -> sP
    const float scale = 0.04419417382415922f;
#pragma unroll
    for (int nt = 0; nt < 4; nt++) {
#pragma unroll
        for (int h = 0; h < 2; h++) {
            int row = wm * 16 + g + 8 * h;
            int i = i0 + row;
#pragma unroll
            for (int cp = 0; cp < 2; cp++) {
                int col = wn * 32 + nt * 8 + t4 * 2 + cp;
                int j = jstart + col;
                float v = accs[nt][h * 2 + cp];
                float s = (j < 0 || j > i) ? -1e30f
                        : v * scale + SLOPE * (float)(j - i);
                sP[row * SP_STR + col] = s;
            }
        }
    }
    __syncthreads();

    // ---- softmax ----
    {
        int r = tid >> 3;
        int l = tid & 7;
        float* row = &sP[r * SP_STR];
        float m = -1e30f;
#pragma unroll
        for (int k = 0; k < 16; k++) m = fmaxf(m, row[l * 16 + k]);
#pragma unroll
        for (int o = 4; o > 0; o >>= 1)
            m = fmaxf(m, __shfl_xor_sync(0xffffffffu, m, o));
        float sum = 0.f;
        float e[16];
#pragma unroll
        for (int k = 0; k < 16; k++) {
            e[k] = __expf(row[l * 16 + k] - m);
            sum += e[k];
        }
#pragma unroll
        for (int o = 4; o > 0; o >>= 1)
            sum += __shfl_xor_sync(0xffffffffu, sum, o);
        float inv = 1.f / sum;
#pragma unroll
        for (int k = 0; k < 16; k++)
            row[l * 16 + k] = __uint_as_float(f2tf32(e[k] * inv));
    }

    // ---- phase 3: O = P @ V, 8 chunks of 64 features, single-buffered V ----
    const uint32_t* sPu = reinterpret_cast<const uint32_t*>(sP);
    const int wn8 = wid >> 1;

    for (int ch = 0; ch < 8; ch++) {
        __syncthreads();   // previous compute done (and, ch=0: softmax done)
        {
            const int e0 = ch * 64;
#pragma unroll
            for (int i = 0; i < 8; i++) {
                int idx = tid + 256 * i;
                int row = idx >> 4, c4 = (idx & 15) << 2;
                int j = jstart + row;
                uint32_t dst = sbase + (W_V0 + row * VC_STR + c4) * 4;
                if (j >= 0) cpa16(dst, &Vb[(size_t)j * 512 + e0 + c4]);
                else sts_zero16(dst);
            }
            CPA_COMMIT();
        }
        CPA_WAIT0();
        __syncthreads();
        const uint32_t* sV = smw + W_V0;

        float acco[2][4];
#pragma unroll
        for (int nt = 0; nt < 2; nt++)
#pragma unroll
            for (int i = 0; i < 4; i++) acco[nt][i] = 0.f;

#pragma unroll
        for (int k8 = 0; k8 < 16; k8++) {
            const int kc = k8 * 8 + t4;
            uint32_t a[4];
            int r = wm * 16 + g;
            a[0] = sPu[r * SP_STR + kc];
            a[1] = sPu[(r + 8) * SP_STR + kc];
            a[2] = sPu[r * SP_STR + kc + 4];
            a[3] = sPu[(r + 8) * SP_STR + kc + 4];
#pragma unroll
            for (int nt = 0; nt < 2; nt++) {
                int nf = wn8 * 16 + nt * 8 + g;
                uint32_t b0 = sV[kc * VC_STR + nf];
                uint32_t b1 = sV[(kc + 4) * VC_STR + nf];
                mma16808(acco[nt], a, b0, b1);
            }
        }

        const int e0 = ch * 64;
#pragma unroll
        for (int nt = 0; nt < 2; nt++) {
            int col = e0 + wn8 * 16 + nt * 8 + t4 * 2;
            int row0 = i0 + wm * 16 + g;
            *reinterpret_cast<float2*>(
                &O[((size_t)b * S_LEN + row0) * 512 + col]) =
                make_float2(acco[nt][0], acco[nt][1]);
            *reinterpret_cast<float2*>(
                &O[((size_t)b * S_LEN + row0 + 8) * 512 + col]) =
                make_float2(acco[nt][2], acco[nt][3]);
        }
    }
}

// ---------------------------------------------------------------------------
extern "C" void kernel_launch(void* const* d_in, const int* in_sizes, int n_in,
                              void* d_out, int out_size)
{
    const float* x   = (const float*)d_in[0];
    const float* Wqk = (const float*)d_in[1];
    const float* Wv  = (const float*)d_in[2];
    const float* bv  = (const float*)d_in[3];
    float* out = (float*)d_out;

    float *Qp = nullptr, *Vp = nullptr;
    cudaGetSymbolAddress((void**)&Qp, g_Q);
    cudaGetSymbolAddress((void**)&Vp, g_V);

    const int gemm_smem = 2 * APLANE * 4;
    cudaFuncSetAttribute(mma_gemm, cudaFuncAttributeMaxDynamicSharedMemorySize,
                         gemm_smem);
    const int attn_smem = ATTN_W * 4;
    cudaFuncSetAttribute(attn_tc, cudaFuncAttributeMaxDynamicSharedMemorySize,
                         attn_smem);

    pack_all<<<10240, 256>>>(x, Wqk, Wv);

    dim3 ggemm(128, 8);
    mma_gemm<<<ggemm, 256, gemm_smem>>>(bv, Qp, Vp);

    dim3 gattn(S_LEN / QT, NB);
    attn_tc<<<gattn, 256, attn_smem>>>(Qp, Vp, out);
}

// round 11
// speedup vs baseline: 1.7886x; 1.7886x over previous
#include <cuda_runtime.h>
#include <cuda_fp16.h>
#include <cstdint>
#include <math.h>

// Problem constants
#define S_LEN 4096
#define D_MODEL 512
#define SLOPE 0.5f
#define QT 32
#define NKEY 128
#define WBACK 96
#define NB 4

// Scratch
__device__ __half g_Xh[NB * S_LEN * D_MODEL];   // X in fp16 (GEMM A + attn K)
__device__ __half g_Qh[NB * S_LEN * D_MODEL];   // Q in fp16 (attn phase-1 A)
__device__ float  g_V [NB * S_LEN * D_MODEL];   // V fp32 tf32-rounded (+bias)
__device__ __half g_Wh[1024 * 512];             // [Wqk | Wv^T] fp16, [n][k]

// ---------------------------------------------------------------------------
// Helpers
// ---------------------------------------------------------------------------
__device__ __forceinline__ void mma16816h(float* d, const uint32_t* a,
                                          uint32_t b0, uint32_t b1)
{
    asm volatile(
        "mma.sync.aligned.m16n8k16.row.col.f32.f16.f16.f32 "
        "{%0,%1,%2,%3}, {%4,%5,%6,%7}, {%8,%9}, {%0,%1,%2,%3};"
        : "+f"(d[0]), "+f"(d[1]), "+f"(d[2]), "+f"(d[3])
        : "r"(a[0]), "r"(a[1]), "r"(a[2]), "r"(a[3]), "r"(b0), "r"(b1));
}

__device__ __forceinline__ void mma16808(float* d, const uint32_t* a,
                                         uint32_t b0, uint32_t b1)
{
    asm volatile(
        "mma.sync.aligned.m16n8k8.row.col.f32.tf32.tf32.f32 "
        "{%0,%1,%2,%3}, {%4,%5,%6,%7}, {%8,%9}, {%0,%1,%2,%3};"
        : "+f"(d[0]), "+f"(d[1]), "+f"(d[2]), "+f"(d[3])
        : "r"(a[0]), "r"(a[1]), "r"(a[2]), "r"(a[3]), "r"(b0), "r"(b1));
}

__device__ __forceinline__ uint32_t f2tf32(float x) {
    uint32_t t;
    asm("cvt.rna.tf32.f32 %0, %1;" : "=r"(t) : "f"(x));
    return t;
}

__device__ __forceinline__ void cpa16(uint32_t dst, const void* src) {
    asm volatile("cp.async.cg.shared.global [%0], [%1], 16;"
                 :: "r"(dst), "l"(src) : "memory");
}
__device__ __forceinline__ void sts_zero16(uint32_t dst) {
    asm volatile("st.shared.v4.b32 [%0], {%1,%1,%1,%1};" :: "r"(dst), "r"(0u)
                 : "memory");
}
#define CPA_COMMIT() asm volatile("cp.async.commit_group;" ::: "memory")
#define CPA_WAIT0()  asm volatile("cp.async.wait_group 0;" ::: "memory")

// ---------------------------------------------------------------------------
// pack_all: X -> fp16 (g_Xh), [Wqk | Wv^T] -> fp16 (g_Wh, [n][k])
// ---------------------------------------------------------------------------
__global__ void pack_all(const float* __restrict__ X,
                         const float* __restrict__ Wqk,
                         const float* __restrict__ Wv)
{
    int bid = blockIdx.x;
    if (bid < 8192) {
        int idx = bid * 256 + threadIdx.x;       // float4 over X
        float4 v = reinterpret_cast<const float4*>(X)[idx];
        __half2 h0 = __floats2half2_rn(v.x, v.y);
        __half2 h1 = __floats2half2_rn(v.z, v.w);
        uint2 t = make_uint2(*(uint32_t*)&h0, *(uint32_t*)&h1);
        *reinterpret_cast<uint2*>(&g_Xh[(size_t)idx * 4]) = t;
    } else {
        int idx = (bid - 8192) * 256 + threadIdx.x;   // 0..524287
        int n = idx >> 9, k = idx & 511;
        float w = (n < 512) ? Wqk[k * 512 + n] : Wv[(n - 512) * 512 + k];
        g_Wh[idx] = __float2half_rn(w);
    }
}

// ---------------------------------------------------------------------------
// fp16 mma GEMM: [Q|V][16384, 1024] = Xh[16384,512] @ Wh^T, m16n8k16.
// CTA 128x128, 8 warps (4m x 2n), K-chunk 64 (4 k16 steps).
// smem: halves packed as u32 words, row stride 36 words -> conflict-free.
// Q written fp16 (g_Qh); V written fp32 tf32-rounded + bias (g_V).
// ---------------------------------------------------------------------------
#define GSTR 36
#define GPLANE (128 * GSTR)

__global__ __launch_bounds__(256)
void mma_gemm(const float* __restrict__ bias,
              __half* __restrict__ Qh, float* __restrict__ V)
{
    extern __shared__ uint32_t smw[];
    uint32_t* sA = smw;
    uint32_t* sB = smw + GPLANE;

    const int tid = threadIdx.x;
    const int wid = tid >> 5;
    const int lane = tid & 31;
    const int g = lane >> 2;
    const int t4 = lane & 3;
    const int warp_m = wid & 3;
    const int warp_n = wid >> 2;
    const int m0 = blockIdx.x * 128;
    const int n0 = blockIdx.y * 128;

    float acc[2][8][4];
#pragma unroll
    for (int mt = 0; mt < 2; mt++)
#pragma unroll
        for (int nt = 0; nt < 8; nt++)
#pragma unroll
            for (int i = 0; i < 4; i++) acc[mt][nt][i] = 0.f;

    for (int c = 0; c < 8; c++) {
        const int k0 = c * 64;     // in halves
        uint4 av[4], bv[4];
#pragma unroll
        for (int i = 0; i < 4; i++) {
            int idx = tid + 256 * i;            // 1024 uint4 per plane
            int row = idx >> 3, h8 = (idx & 7) * 8;
            av[i] = *reinterpret_cast<const uint4*>(
                &g_Xh[(size_t)(m0 + row) * 512 + k0 + h8]);
            bv[i] = *reinterpret_cast<const uint4*>(
                &g_Wh[(size_t)(n0 + row) * 512 + k0 + h8]);
        }
        if (c) __syncthreads();
#pragma unroll
        for (int i = 0; i < 4; i++) {
            int idx = tid + 256 * i;
            int row = idx >> 3, w4 = (idx & 7) * 4;
            *reinterpret_cast<uint4*>(&sA[row * GSTR + w4]) = av[i];
            *reinterpret_cast<uint4*>(&sB[row * GSTR + w4]) = bv[i];
        }
        __syncthreads();

#pragma unroll
        for (int s = 0; s < 4; s++) {          // k16 steps
            const int kc = s * 8 + t4;
            uint32_t a[2][4];
#pragma unroll
            for (int mt = 0; mt < 2; mt++) {
                int r = warp_m * 32 + mt * 16 + g;
                a[mt][0] = sA[r * GSTR + kc];
                a[mt][1] = sA[(r + 8) * GSTR + kc];
                a[mt][2] = sA[r * GSTR + kc + 4];
                a[mt][3] = sA[(r + 8) * GSTR + kc + 4];
            }
#pragma unroll
            for (int nt = 0; nt < 8; nt++) {
                int rn = warp_n * 64 + nt * 8 + g;
                uint32_t b0 = sB[rn * GSTR + kc];
                uint32_t b1 = sB[rn * GSTR + kc + 4];
#pragma unroll
                for (int mt = 0; mt < 2; mt++)
                    mma16816h(acc[mt][nt], a[mt], b0, b1);
            }
        }
    }

#pragma unroll
    for (int mt = 0; mt < 2; mt++) {
        int row0 = m0 + warp_m * 32 + mt * 16 + g;
#pragma unroll
        for (int nt = 0; nt < 8; nt++) {
            int col = n0 + warp_n * 64 + nt * 8 + t4 * 2;
            if (col < 512) {
                __half2 lo = __floats2half2_rn(acc[mt][nt][0], acc[mt][nt][1]);
                __half2 hi = __floats2half2_rn(acc[mt][nt][2], acc[mt][nt][3]);
                *reinterpret_cast<uint32_t*>(&Qh[(size_t)row0 * 512 + col]) =
                    *(uint32_t*)&lo;
                *reinterpret_cast<uint32_t*>(&Qh[(size_t)(row0 + 8) * 512 + col]) =
                    *(uint32_t*)&hi;
            } else {
                int vc = col - 512;
                float2 b2 = *reinterpret_cast<const float2*>(&bias[vc]);
                float2 lo = make_float2(
                    __uint_as_float(f2tf32(acc[mt][nt][0] + b2.x)),
                    __uint_as_float(f2tf32(acc[mt][nt][1] + b2.y)));
                float2 hi = make_float2(
                    __uint_as_float(f2tf32(acc[mt][nt][2] + b2.x)),
                    __uint_as_float(f2tf32(acc[mt][nt][3] + b2.y)));
                *reinterpret_cast<float2*>(&V[(size_t)row0 * 512 + vc]) = lo;
                *reinterpret_cast<float2*>(&V[(size_t)(row0 + 8) * 512 + vc]) = hi;
            }
        }
    }
}

// ---------------------------------------------------------------------------
// Windowed attention. Phase1: fp16 m16n8k16 QK^T (64-col double-buffered
// chunks). Phase2: softmax. Phase3: tf32 PV (double-buffered fp32 V chunks).
// CTA = 32 queries x 128-key band, 8 warps, occ 2 (90.6 KB smem).
// ---------------------------------------------------------------------------
#define SP_STR 132
#define HQ_STR 36              // fp16 chunk row stride (words = half2)
#define VC_STR 72
#define W_Q0 4224
#define W_K0 (W_Q0 + 32 * HQ_STR)        // 5376
#define W_Q1 (W_K0 + 128 * HQ_STR)       // 9984
#define W_K1 (W_Q1 + 32 * HQ_STR)        // 11136
#define W_V0 4224                        // aliased over phase-1 buffers
#define W_V1 (W_V0 + 128 * VC_STR)       // 13440
#define ATTN_W (W_V1 + 128 * VC_STR)     // 22656 words = 90624 B

__global__ __launch_bounds__(256, 2)
void attn_tc(const float* __restrict__ V, float* __restrict__ O)
{
    extern __shared__ uint32_t smw[];
    float* sP = reinterpret_cast<float*>(smw);
    const uint32_t sbase = (uint32_t)__cvta_generic_to_shared(smw);

    const int tid = threadIdx.x;
    const int wid = tid >> 5;
    const int lane = tid & 31;
    const int g = lane >> 2;
    const int t4 = lane & 3;
    const int b  = blockIdx.y;
    const int i0 = blockIdx.x * QT;
    const int jstart = i0 - WBACK;

    const __half* Qb = g_Qh + (size_t)b * S_LEN * D_MODEL;
    const __half* Kb = g_Xh + (size_t)b * S_LEN * D_MODEL;
    const float*  Vb = V + (size_t)b * S_LEN * D_MODEL;

    const int wm = wid & 1;
    const int wn = wid >> 1;      // 0..3

    // ---- phase-1 loaders: chunk = 64 halves (32 words) per row ----
    const int qrow = tid >> 3;            // 0..31
    const int qu4  = tid & 7;             // uint4 within row

    // prologue: chunk 0
    {
        cpa16(sbase + (W_Q0 + qrow * HQ_STR + qu4 * 4) * 4,
              &Qb[(size_t)(i0 + qrow) * 512 + 0 + qu4 * 8]);
#pragma unroll
        for (int i = 0; i < 4; i++) {
            int idx = tid + 256 * i;
            int row = idx >> 3, u4 = idx & 7;
            int j = jstart + row;
            uint32_t dst = sbase + (W_K0 + row * HQ_STR + u4 * 4) * 4;
            if (j >= 0) cpa16(dst, &Kb[(size_t)j * 512 + 0 + u4 * 8]);
            else sts_zero16(dst);
        }
        CPA_COMMIT();
    }

    float accs[4][4];
#pragma unroll
    for (int nt = 0; nt < 4; nt++)
#pragma unroll
        for (int i = 0; i < 4; i++) accs[nt][i] = 0.f;

    for (int c = 0; c < 8; c++) {
        CPA_WAIT0();
        __syncthreads();
        if (c < 7) {
            const int k0 = (c + 1) * 64;
            const int wq = ((c + 1) & 1) ? W_Q1 : W_Q0;
            const int wk = ((c + 1) & 1) ? W_K1 : W_K0;
            cpa16(sbase + (wq + qrow * HQ_STR + qu4 * 4) * 4,
                  &Qb[(size_t)(i0 + qrow) * 512 + k0 + qu4 * 8]);
#pragma unroll
            for (int i = 0; i < 4; i++) {
                int idx = tid + 256 * i;
                int row = idx >> 3, u4 = idx & 7;
                int j = jstart + row;
                uint32_t dst = sbase + (wk + row * HQ_STR + u4 * 4) * 4;
                if (j >= 0) cpa16(dst, &Kb[(size_t)j * 512 + k0 + u4 * 8]);
                else sts_zero16(dst);
            }
            CPA_COMMIT();
        }
        const uint32_t* sQ = smw + ((c & 1) ? W_Q1 : W_Q0);
        const uint32_t* sK = smw + ((c & 1) ? W_K1 : W_K0);
#pragma unroll
        for (int s = 0; s < 4; s++) {          // k16 steps
            const int kc = s * 8 + t4;
            uint32_t a[4];
            int r = wm * 16 + g;
            a[0] = sQ[r * HQ_STR + kc];
            a[1] = sQ[(r + 8) * HQ_STR + kc];
            a[2] = sQ[r * HQ_STR + kc + 4];
            a[3] = sQ[(r + 8) * HQ_STR + kc + 4];
#pragma unroll
            for (int nt = 0; nt < 4; nt++) {
                int rn = wn * 32 + nt * 8 + g;
                uint32_t b0 = sK[rn * HQ_STR + kc];
                uint32_t b1 = sK[rn * HQ_STR + kc + 4];
                mma16816h(accs[nt], a, b0, b1);
            }
        }
    }

    // scale + ALiBi + causal mask -> sP (fp32)
    const float scale = 0.04419417382415922f;
#pragma unroll
    for (int nt = 0; nt < 4; nt++) {
#pragma unroll
        for (int h = 0; h < 2; h++) {
            int row = wm * 16 + g + 8 * h;
            int i = i0 + row;
#pragma unroll
            for (int cp = 0; cp < 2; cp++) {
                int col = wn * 32 + nt * 8 + t4 * 2 + cp;
                int j = jstart + col;
                float v = accs[nt][h * 2 + cp];
                float s = (j < 0 || j > i) ? -1e30f
                        : v * scale + SLOPE * (float)(j - i);
                sP[row * SP_STR + col] = s;
            }
        }
    }
    __syncthreads();

    // ---- issue V chunk 0 (overlaps softmax) ----
    {
#pragma unroll
        for (int i = 0; i < 8; i++) {
            int idx = tid + 256 * i;
            int row = idx >> 4, c4 = (idx & 15) << 2;
            int j = jstart + row;
            uint32_t dst = sbase + (W_V0 + row * VC_STR + c4) * 4;
            if (j >= 0) cpa16(dst, &Vb[(size_t)j * 512 + 0 + c4]);
            else sts_zero16(dst);
        }
        CPA_COMMIT();
    }

    // ---- softmax ----
    {
        int r = tid >> 3;
        int l = tid & 7;
        float* row = &sP[r * SP_STR];
        float m = -1e30f;
#pragma unroll
        for (int k = 0; k < 16; k++) m = fmaxf(m, row[l * 16 + k]);
#pragma unroll
        for (int o = 4; o > 0; o >>= 1)
            m = fmaxf(m, __shfl_xor_sync(0xffffffffu, m, o));
        float sum = 0.f;
        float e[16];
#pragma unroll
        for (int k = 0; k < 16; k++) {
            e[k] = __expf(row[l * 16 + k] - m);
            sum += e[k];
        }
#pragma unroll
        for (int o = 4; o > 0; o >>= 1)
            sum += __shfl_xor_sync(0xffffffffu, sum, o);
        float inv = 1.f / sum;
#pragma unroll
        for (int k = 0; k < 16; k++)
            row[l * 16 + k] = __uint_as_float(f2tf32(e[k] * inv));
    }
    __syncthreads();

    // ---- P fragments -> registers ----
    const uint32_t* sPu = reinterpret_cast<const uint32_t*>(sP);
    uint32_t pa[16][4];
    {
        int r = wm * 16 + g;
#pragma unroll
        for (int k8 = 0; k8 < 16; k8++) {
            int kc = k8 * 8 + t4;
            pa[k8][0] = sPu[r * SP_STR + kc];
            pa[k8][1] = sPu[(r + 8) * SP_STR + kc];
            pa[k8][2] = sPu[r * SP_STR + kc + 4];
            pa[k8][3] = sPu[(r + 8) * SP_STR + kc + 4];
        }
    }

    // ---- phase 3: O = P @ V (tf32), 64-feature double-buffered chunks ----
    const int wn8 = wid >> 1;
    for (int ch = 0; ch < 8; ch++) {
        CPA_WAIT0();
        __syncthreads();
        if (ch < 7) {
            const int e0 = (ch + 1) * 64;
            const int wv = ((ch + 1) & 1) ? W_V1 : W_V0;
#pragma unroll
            for (int i = 0; i < 8; i++) {
                int idx = tid + 256 * i;
                int row = idx >> 4, c4 = (idx & 15) << 2;
                int j = jstart + row;
                uint32_t dst = sbase + (wv + row * VC_STR + c4) * 4;
                if (j >= 0) cpa16(dst, &Vb[(size_t)j * 512 + e0 + c4]);
                else sts_zero16(dst);
            }
            CPA_COMMIT();
        }
        const uint32_t* sV = smw + ((ch & 1) ? W_V1 : W_V0);

        float acco[2][4];
#pragma unroll
        for (int nt = 0; nt < 2; nt++)
#pragma unroll
            for (int i = 0; i < 4; i++) acco[nt][i] = 0.f;

#pragma unroll
        for (int k8 = 0; k8 < 16; k8++) {
            const int kr = k8 * 8 + t4;
#pragma unroll
            for (int nt = 0; nt < 2; nt++) {
                int nf = wn8 * 16 + nt * 8 + g;
                uint32_t b0 = sV[kr * VC_STR + nf];
                uint32_t b1 = sV[(kr + 4) * VC_STR + nf];
                mma16808(acco[nt], pa[k8], b0, b1);
            }
        }

        const int e0 = ch * 64;
#pragma unroll
        for (int nt = 0; nt < 2; nt++) {
            int col = e0 + wn8 * 16 + nt * 8 + t4 * 2;
            int row0 = i0 + wm * 16 + g;
            *reinterpret_cast<float2*>(
                &O[((size_t)b * S_LEN + row0) * 512 + col]) =
                make_float2(acco[nt][0], acco[nt][1]);
            *reinterpret_cast<float2*>(
                &O[((size_t)b * S_LEN + row0 + 8) * 512 + col]) =
                make_float2(acco[nt][2], acco[nt][3]);
        }
    }
}

// ---------------------------------------------------------------------------
extern "C" void kernel_launch(void* const* d_in, const int* in_sizes, int n_in,
                              void* d_out, int out_size)
{
    const float* x   = (const float*)d_in[0];
    const float* Wqk = (const float*)d_in[1];
    const float* Wv  = (const float*)d_in[2];
    const float* bv  = (const float*)d_in[3];
    float* out = (float*)d_out;

    __half* Qhp = nullptr;
    float*  Vp  = nullptr;
    cudaGetSymbolAddress((void**)&Qhp, g_Qh);
    cudaGetSymbolAddress((void**)&Vp,  g_V);

    const int gemm_smem = 2 * GPLANE * 4;   // 36864 B
    cudaFuncSetAttribute(mma_gemm, cudaFuncAttributeMaxDynamicSharedMemorySize,
                         gemm_smem);
    const int attn_smem = ATTN_W * 4;       // 90624 B
    cudaFuncSetAttribute(attn_tc, cudaFuncAttributeMaxDynamicSharedMemorySize,
                         attn_smem);

    pack_all<<<10240, 256>>>(x, Wqk, Wv);

    dim3 ggemm(128, 8);
    mma_gemm<<<ggemm, 256, gemm_smem>>>(bv, Qhp, Vp);

    dim3 gattn(S_LEN / QT, NB);
    attn_tc<<<gattn, 256, attn_smem>>>(Vp, out);
}

// round 12
// speedup vs baseline: 1.9353x; 1.0820x over previous
#include <cuda_runtime.h>
#include <cuda_fp16.h>
#include <cstdint>
#include <math.h>

// Problem constants
#define S_LEN 4096
#define D_MODEL 512
#define SLOPE 0.5f
#define QT 32
#define NKEY 128
#define WBACK 96
#define NB 4

// Scratch
__device__ __half g_Xh[NB * S_LEN * D_MODEL];   // X in fp16 (GEMM A + attn K)
__device__ __half g_Qh[NB * S_LEN * D_MODEL];   // Q in fp16 (attn phase-1 A)
__device__ __half g_Vh[NB * S_LEN * D_MODEL];   // V in fp16 (+bias)
__device__ __half g_Wh[1024 * 512];             // [Wqk | Wv^T] fp16, [n][k]

// ---------------------------------------------------------------------------
// Helpers
// ---------------------------------------------------------------------------
__device__ __forceinline__ void mma16816h(float* d, const uint32_t* a,
                                          uint32_t b0, uint32_t b1)
{
    asm volatile(
        "mma.sync.aligned.m16n8k16.row.col.f32.f16.f16.f32 "
        "{%0,%1,%2,%3}, {%4,%5,%6,%7}, {%8,%9}, {%0,%1,%2,%3};"
        : "+f"(d[0]), "+f"(d[1]), "+f"(d[2]), "+f"(d[3])
        : "r"(a[0]), "r"(a[1]), "r"(a[2]), "r"(a[3]), "r"(b0), "r"(b1));
}

__device__ __forceinline__ void ldsm_x4_trans(uint32_t& r0, uint32_t& r1,
                                              uint32_t& r2, uint32_t& r3,
                                              uint32_t addr)
{
    asm volatile(
        "ldmatrix.sync.aligned.m8n8.x4.trans.shared.b16 {%0,%1,%2,%3}, [%4];"
        : "=r"(r0), "=r"(r1), "=r"(r2), "=r"(r3) : "r"(addr));
}

__device__ __forceinline__ void cpa16(uint32_t dst, const void* src) {
    asm volatile("cp.async.cg.shared.global [%0], [%1], 16;"
                 :: "r"(dst), "l"(src) : "memory");
}
__device__ __forceinline__ void sts_zero16(uint32_t dst) {
    asm volatile("st.shared.v4.b32 [%0], {%1,%1,%1,%1};" :: "r"(dst), "r"(0u)
                 : "memory");
}
#define CPA_COMMIT() asm volatile("cp.async.commit_group;" ::: "memory")
#define CPA_WAIT0()  asm volatile("cp.async.wait_group 0;" ::: "memory")

// ---------------------------------------------------------------------------
// pack_all: X -> fp16 (g_Xh), [Wqk | Wv^T] -> fp16 (g_Wh, [n][k])
// ---------------------------------------------------------------------------
__global__ void pack_all(const float* __restrict__ X,
                         const float* __restrict__ Wqk,
                         const float* __restrict__ Wv)
{
    int bid = blockIdx.x;
    if (bid < 8192) {
        int idx = bid * 256 + threadIdx.x;       // float4 over X
        float4 v = reinterpret_cast<const float4*>(X)[idx];
        __half2 h0 = __floats2half2_rn(v.x, v.y);
        __half2 h1 = __floats2half2_rn(v.z, v.w);
        uint2 t = make_uint2(*(uint32_t*)&h0, *(uint32_t*)&h1);
        *reinterpret_cast<uint2*>(&g_Xh[(size_t)idx * 4]) = t;
    } else {
        int idx = (bid - 8192) * 256 + threadIdx.x;   // 0..524287
        int n = idx >> 9, k = idx & 511;
        float w = (n < 512) ? Wqk[k * 512 + n] : Wv[(n - 512) * 512 + k];
        g_Wh[idx] = __float2half_rn(w);
    }
}

// ---------------------------------------------------------------------------
// fp16 mma GEMM: [Q|V][16384, 1024] = Xh[16384,512] @ Wh^T, m16n8k16.
// Q written fp16 (g_Qh); V written fp16 + bias (g_Vh).
// ---------------------------------------------------------------------------
#define GSTR 36
#define GPLANE (128 * GSTR)

__global__ __launch_bounds__(256)
void mma_gemm(const float* __restrict__ bias,
              __half* __restrict__ Qh, __half* __restrict__ Vh)
{
    extern __shared__ uint32_t smw[];
    uint32_t* sA = smw;
    uint32_t* sB = smw + GPLANE;

    const int tid = threadIdx.x;
    const int wid = tid >> 5;
    const int lane = tid & 31;
    const int g = lane >> 2;
    const int t4 = lane & 3;
    const int warp_m = wid & 3;
    const int warp_n = wid >> 2;
    const int m0 = blockIdx.x * 128;
    const int n0 = blockIdx.y * 128;

    float acc[2][8][4];
#pragma unroll
    for (int mt = 0; mt < 2; mt++)
#pragma unroll
        for (int nt = 0; nt < 8; nt++)
#pragma unroll
            for (int i = 0; i < 4; i++) acc[mt][nt][i] = 0.f;

    for (int c = 0; c < 8; c++) {
        const int k0 = c * 64;     // in halves
        uint4 av[4], bv[4];
#pragma unroll
        for (int i = 0; i < 4; i++) {
            int idx = tid + 256 * i;
            int row = idx >> 3, h8 = (idx & 7) * 8;
            av[i] = *reinterpret_cast<const uint4*>(
                &g_Xh[(size_t)(m0 + row) * 512 + k0 + h8]);
            bv[i] = *reinterpret_cast<const uint4*>(
                &g_Wh[(size_t)(n0 + row) * 512 + k0 + h8]);
        }
        if (c) __syncthreads();
#pragma unroll
        for (int i = 0; i < 4; i++) {
            int idx = tid + 256 * i;
            int row = idx >> 3, w4 = (idx & 7) * 4;
            *reinterpret_cast<uint4*>(&sA[row * GSTR + w4]) = av[i];
            *reinterpret_cast<uint4*>(&sB[row * GSTR + w4]) = bv[i];
        }
        __syncthreads();

#pragma unroll
        for (int s = 0; s < 4; s++) {
            const int kc = s * 8 + t4;
            uint32_t a[2][4];
#pragma unroll
            for (int mt = 0; mt < 2; mt++) {
                int r = warp_m * 32 + mt * 16 + g;
                a[mt][0] = sA[r * GSTR + kc];
                a[mt][1] = sA[(r + 8) * GSTR + kc];
                a[mt][2] = sA[r * GSTR + kc + 4];
                a[mt][3] = sA[(r + 8) * GSTR + kc + 4];
            }
#pragma unroll
            for (int nt = 0; nt < 8; nt++) {
                int rn = warp_n * 64 + nt * 8 + g;
                uint32_t b0 = sB[rn * GSTR + kc];
                uint32_t b1 = sB[rn * GSTR + kc + 4];
#pragma unroll
                for (int mt = 0; mt < 2; mt++)
                    mma16816h(acc[mt][nt], a[mt], b0, b1);
            }
        }
    }

#pragma unroll
    for (int mt = 0; mt < 2; mt++) {
        int row0 = m0 + warp_m * 32 + mt * 16 + g;
#pragma unroll
        for (int nt = 0; nt < 8; nt++) {
            int col = n0 + warp_n * 64 + nt * 8 + t4 * 2;
            if (col < 512) {
                __half2 lo = __floats2half2_rn(acc[mt][nt][0], acc[mt][nt][1]);
                __half2 hi = __floats2half2_rn(acc[mt][nt][2], acc[mt][nt][3]);
                *reinterpret_cast<uint32_t*>(&Qh[(size_t)row0 * 512 + col]) =
                    *(uint32_t*)&lo;
                *reinterpret_cast<uint32_t*>(&Qh[(size_t)(row0 + 8) * 512 + col]) =
                    *(uint32_t*)&hi;
            } else {
                int vc = col - 512;
                float2 b2 = *reinterpret_cast<const float2*>(&bias[vc]);
                __half2 lo = __floats2half2_rn(acc[mt][nt][0] + b2.x,
                                               acc[mt][nt][1] + b2.y);
                __half2 hi = __floats2half2_rn(acc[mt][nt][2] + b2.x,
                                               acc[mt][nt][3] + b2.y);
                *reinterpret_cast<uint32_t*>(&Vh[(size_t)row0 * 512 + vc]) =
                    *(uint32_t*)&lo;
                *reinterpret_cast<uint32_t*>(&Vh[(size_t)(row0 + 8) * 512 + vc]) =
                    *(uint32_t*)&hi;
            }
        }
    }
}

// ---------------------------------------------------------------------------
// Windowed attention, all-fp16 MMA. CTA = 32 q x 128-key band, 8 warps.
// Phase1: fp16 QK^T, 64-col double-buffered chunks.
// Phase2: softmax; P packed fp16 half2-k pairs into sPh.
// Phase3: fp16 PV with ldmatrix.x4.trans on row-major V chunks (fp16).
// Smem (words): sP[32][132]@0; sPh[32][68]@4224; phase1 Q0/K0/Q1/K1 @6400
// (stride 36); phase3 V0/V1 aliased @6400 (rows of 72 halves = 36 words).
// Total 17920 words = 71680 B, occupancy 2.
// ---------------------------------------------------------------------------
#define SP_STR 132
#define PH_STR 68              // sPh row stride in words (64 pairs + pad)
#define HQ_STR 36              // phase-1 fp16 chunk row stride (words)
#define VH_STR 72              // phase-3 V row stride in halves
#define W_PH 4224
#define W_Q0 6400
#define W_K0 (W_Q0 + 32 * HQ_STR)        // 7552
#define W_Q1 (W_K0 + 128 * HQ_STR)       // 12160
#define W_K1 (W_Q1 + 32 * HQ_STR)        // 13312
#define W_V0 6400                        // aliased over phase-1 buffers
#define W_V1 (W_V0 + 128 * (VH_STR / 2)) // 11008
#define ATTN_W (W_K1 + 128 * HQ_STR)     // 17920 words

__global__ __launch_bounds__(256, 2)
void attn_tc(float* __restrict__ O)
{
    extern __shared__ uint32_t smw[];
    float* sP = reinterpret_cast<float*>(smw);
    uint32_t* sPh = smw + W_PH;
    const uint32_t sbase = (uint32_t)__cvta_generic_to_shared(smw);

    const int tid = threadIdx.x;
    const int wid = tid >> 5;
    const int lane = tid & 31;
    const int g = lane >> 2;
    const int t4 = lane & 3;
    const int b  = blockIdx.y;
    const int i0 = blockIdx.x * QT;
    const int jstart = i0 - WBACK;

    const __half* Qb = g_Qh + (size_t)b * S_LEN * D_MODEL;
    const __half* Kb = g_Xh + (size_t)b * S_LEN * D_MODEL;
    const __half* Vb = g_Vh + (size_t)b * S_LEN * D_MODEL;

    const int wm = wid & 1;
    const int wn = wid >> 1;      // 0..3

    const int qrow = tid >> 3;            // 0..31
    const int qu4  = tid & 7;

    // prologue: phase-1 chunk 0
    {
        cpa16(sbase + (W_Q0 + qrow * HQ_STR + qu4 * 4) * 4,
              &Qb[(size_t)(i0 + qrow) * 512 + 0 + qu4 * 8]);
#pragma unroll
        for (int i = 0; i < 4; i++) {
            int idx = tid + 256 * i;
            int row = idx >> 3, u4 = idx & 7;
            int j = jstart + row;
            uint32_t dst = sbase + (W_K0 + row * HQ_STR + u4 * 4) * 4;
            if (j >= 0) cpa16(dst, &Kb[(size_t)j * 512 + 0 + u4 * 8]);
            else sts_zero16(dst);
        }
        CPA_COMMIT();
    }

    float accs[4][4];
#pragma unroll
    for (int nt = 0; nt < 4; nt++)
#pragma unroll
        for (int i = 0; i < 4; i++) accs[nt][i] = 0.f;

    for (int c = 0; c < 8; c++) {
        CPA_WAIT0();
        __syncthreads();
        if (c < 7) {
            const int k0 = (c + 1) * 64;
            const int wq = ((c + 1) & 1) ? W_Q1 : W_Q0;
            const int wk = ((c + 1) & 1) ? W_K1 : W_K0;
            cpa16(sbase + (wq + qrow * HQ_STR + qu4 * 4) * 4,
                  &Qb[(size_t)(i0 + qrow) * 512 + k0 + qu4 * 8]);
#pragma unroll
            for (int i = 0; i < 4; i++) {
                int idx = tid + 256 * i;
                int row = idx >> 3, u4 = idx & 7;
                int j = jstart + row;
                uint32_t dst = sbase + (wk + row * HQ_STR + u4 * 4) * 4;
                if (j >= 0) cpa16(dst, &Kb[(size_t)j * 512 + k0 + u4 * 8]);
                else sts_zero16(dst);
            }
            CPA_COMMIT();
        }
        const uint32_t* sQ = smw + ((c & 1) ? W_Q1 : W_Q0);
        const uint32_t* sK = smw + ((c & 1) ? W_K1 : W_K0);
#pragma unroll
        for (int s = 0; s < 4; s++) {
            const int kc = s * 8 + t4;
            uint32_t a[4];
            int r = wm * 16 + g;
            a[0] = sQ[r * HQ_STR + kc];
            a[1] = sQ[(r + 8) * HQ_STR + kc];
            a[2] = sQ[r * HQ_STR + kc + 4];
            a[3] = sQ[(r + 8) * HQ_STR + kc + 4];
#pragma unroll
            for (int nt = 0; nt < 4; nt++) {
                int rn = wn * 32 + nt * 8 + g;
                uint32_t b0 = sK[rn * HQ_STR + kc];
                uint32_t b1 = sK[rn * HQ_STR + kc + 4];
                mma16816h(accs[nt], a, b0, b1);
            }
        }
    }

    // scale + ALiBi + causal mask -> sP (fp32)
    const float scale = 0.04419417382415922f;
#pragma unroll
    for (int nt = 0; nt < 4; nt++) {
#pragma unroll
        for (int h = 0; h < 2; h++) {
            int row = wm * 16 + g + 8 * h;
            int i = i0 + row;
#pragma unroll
            for (int cp = 0; cp < 2; cp++) {
                int col = wn * 32 + nt * 8 + t4 * 2 + cp;
                int j = jstart + col;
                float v = accs[nt][h * 2 + cp];
                float s = (j < 0 || j > i) ? -1e30f
                        : v * scale + SLOPE * (float)(j - i);
                sP[row * SP_STR + col] = s;
            }
        }
    }
    __syncthreads();

    // ---- issue V chunk 0 (fp16, overlaps softmax) ----
    {
#pragma unroll
        for (int i = 0; i < 4; i++) {
            int idx = tid + 256 * i;          // 1024 cp16: 128 rows x 8
            int row = idx >> 3, u4 = idx & 7;
            int j = jstart + row;
            uint32_t dst = sbase + W_V0 * 4 + (row * VH_STR + u4 * 8) * 2;
            if (j >= 0) cpa16(dst, &Vb[(size_t)j * 512 + 0 + u4 * 8]);
            else sts_zero16(dst);
        }
        CPA_COMMIT();
    }

    // ---- softmax; pack P to fp16 pairs in sPh ----
    {
        int r = tid >> 3;
        int l = tid & 7;
        float* row = &sP[r * SP_STR];
        float m = -1e30f;
#pragma unroll
        for (int k = 0; k < 16; k++) m = fmaxf(m, row[l * 16 + k]);
#pragma unroll
        for (int o = 4; o > 0; o >>= 1)
            m = fmaxf(m, __shfl_xor_sync(0xffffffffu, m, o));
        float sum = 0.f;
        float e[16];
#pragma unroll
        for (int k = 0; k < 16; k++) {
            e[k] = __expf(row[l * 16 + k] - m);
            sum += e[k];
        }
#pragma unroll
        for (int o = 4; o > 0; o >>= 1)
            sum += __shfl_xor_sync(0xffffffffu, sum, o);
        float inv = 1.f / sum;
#pragma unroll
        for (int k = 0; k < 8; k++) {
            __half2 h2 = __floats2half2_rn(e[2 * k] * inv, e[2 * k + 1] * inv);
            sPh[r * PH_STR + l * 8 + k] = *(uint32_t*)&h2;
        }
    }
    __syncthreads();

    // ---- P fragments -> registers (8 k16 steps) ----
    uint32_t pa[8][4];
    {
        int r = wm * 16 + g;
#pragma unroll
        for (int s = 0; s < 8; s++) {
            int kc = s * 8 + t4;
            pa[s][0] = sPh[r * PH_STR + kc];
            pa[s][1] = sPh[(r + 8) * PH_STR + kc];
            pa[s][2] = sPh[r * PH_STR + kc + 4];
            pa[s][3] = sPh[(r + 8) * PH_STR + kc + 4];
        }
    }

    // ---- phase 3: O = P @ V (fp16 via ldmatrix.trans) ----
    const int wn8 = wid >> 1;          // 0..3 -> 16 features
    // ldmatrix lane address: rows kt + lane%16, col group nf0 + (lane>>4)*8
    const int lrow = lane & 15;
    const int lcolg = (lane >> 4) * 8;

    for (int ch = 0; ch < 8; ch++) {
        CPA_WAIT0();
        __syncthreads();
        if (ch < 7) {
            const int e0 = (ch + 1) * 64;
            const int wv = ((ch + 1) & 1) ? W_V1 : W_V0;
#pragma unroll
            for (int i = 0; i < 4; i++) {
                int idx = tid + 256 * i;
                int row = idx >> 3, u4 = idx & 7;
                int j = jstart + row;
                uint32_t dst = sbase + wv * 4 + (row * VH_STR + u4 * 8) * 2;
                if (j >= 0) cpa16(dst, &Vb[(size_t)j * 512 + e0 + u4 * 8]);
                else sts_zero16(dst);
            }
            CPA_COMMIT();
        }
        const uint32_t vbase = sbase + ((ch & 1) ? W_V1 : W_V0) * 4;

        float acco[2][4];
#pragma unroll
        for (int nt = 0; nt < 2; nt++)
#pragma unroll
            for (int i = 0; i < 4; i++) acco[nt][i] = 0.f;

#pragma unroll
        for (int s = 0; s < 8; s++) {          // k16 over 128 tokens
            uint32_t r0, r1, r2, r3;
            uint32_t addr = vbase +
                ((s * 16 + lrow) * VH_STR + wn8 * 16 + lcolg) * 2;
            ldsm_x4_trans(r0, r1, r2, r3, addr);
            mma16816h(acco[0], pa[s], r0, r1);
            mma16816h(acco[1], pa[s], r2, r3);
        }

        const int e0 = ch * 64;
#pragma unroll
        for (int nt = 0; nt < 2; nt++) {
            int col = e0 + wn8 * 16 + nt * 8 + t4 * 2;
            int row0 = i0 + wm * 16 + g;
            *reinterpret_cast<float2*>(
                &O[((size_t)b * S_LEN + row0) * 512 + col]) =
                make_float2(acco[nt][0], acco[nt][1]);
            *reinterpret_cast<float2*>(
                &O[((size_t)b * S_LEN + row0 + 8) * 512 + col]) =
                make_float2(acco[nt][2], acco[nt][3]);
        }
    }
}

// ---------------------------------------------------------------------------
extern "C" void kernel_launch(void* const* d_in, const int* in_sizes, int n_in,
                              void* d_out, int out_size)
{
    const float* x   = (const float*)d_in[0];
    const float* Wqk = (const float*)d_in[1];
    const float* Wv  = (const float*)d_in[2];
    const float* bv  = (const float*)d_in[3];
    float* out = (float*)d_out;

    __half *Qhp = nullptr, *Vhp = nullptr;
    cudaGetSymbolAddress((void**)&Qhp, g_Qh);
    cudaGetSymbolAddress((void**)&Vhp, g_Vh);

    const int gemm_smem = 2 * GPLANE * 4;   // 36864 B
    cudaFuncSetAttribute(mma_gemm, cudaFuncAttributeMaxDynamicSharedMemorySize,
                         gemm_smem);
    const int attn_smem = ATTN_W * 4;       // 71680 B
    cudaFuncSetAttribute(attn_tc, cudaFuncAttributeMaxDynamicSharedMemorySize,
                         attn_smem);

    pack_all<<<10240, 256>>>(x, Wqk, Wv);

    dim3 ggemm(128, 8);
    mma_gemm<<<ggemm, 256, gemm_smem>>>(bv, Qhp, Vhp);

    dim3 gattn(S_LEN / QT, NB);
    attn_tc<<<gattn, 256, attn_smem>>>(out);
}